// round 4
// baseline (speedup 1.0000x reference)
#include <cuda_runtime.h>
#include <math.h>

// Problem constants (fixed by the dataset): C=256 channels.
#define CCH   256
#define WR    32      // rows per warp
#define MAXB  8       // scenes
#define NPART 256     // partial-sum blocks for scene means

__device__ float g_part[NPART][MAXB * 3];
__device__ float g_mean[MAXB * 3];
__device__ int   g_offs[MAXB + 1];
__device__ float g_len[MAXB];

// ---------------------------------------------------------------------------
// Kernel 0: resolve lengths dtype (int32 vs int64) and build prefix offsets.
// Deterministic, single thread, trivial cost.
// ---------------------------------------------------------------------------
__global__ void k_offs(const void* __restrict__ lengths_raw, int n, int b)
{
    const long long* l64 = (const long long*)lengths_raw;
    const int*       l32 = (const int*)lengths_raw;
    long long s64 = 0;
    for (int i = 0; i < b; i++) s64 += l64[i];
    bool is64 = (s64 == (long long)n);

    int o = 0;
    g_offs[0] = 0;
    for (int s = 0; s < MAXB; s++) {
        long long L = 0;
        if (s < b) L = is64 ? l64[s] : (long long)l32[s];
        o += (int)L;
        g_offs[s + 1] = (s < b) ? o : n;
        if (s < b) g_len[s] = (float)((L < 1) ? 1 : L);
        else       g_len[s] = 1.0f;
    }
}

// ---------------------------------------------------------------------------
// Kernel 1: deterministic per-block partial sums of coords per scene.
// ---------------------------------------------------------------------------
__global__ __launch_bounds__(256) void k_partial(
    const float* __restrict__ coord, int n, int b)
{
    int offs[MAXB + 1];
#pragma unroll
    for (int s = 0; s <= MAXB; s++) offs[s] = g_offs[s];

    float acc[MAXB][3];
#pragma unroll
    for (int s = 0; s < MAXB; s++) { acc[s][0] = 0.f; acc[s][1] = 0.f; acc[s][2] = 0.f; }

    int rows_per_block = (n + gridDim.x - 1) / gridDim.x;
    int r0 = blockIdx.x * rows_per_block;
    int r1 = min(r0 + rows_per_block, n);

    for (int r = r0 + (int)threadIdx.x; r < r1; r += blockDim.x) {
        float x = coord[3 * r + 0];
        float y = coord[3 * r + 1];
        float z = coord[3 * r + 2];
        int seg = 0;
#pragma unroll
        for (int s = 1; s < MAXB; s++) if (s < b && r >= offs[s]) seg = s;
        acc[seg][0] += x; acc[seg][1] += y; acc[seg][2] += z;
    }

    __shared__ float sm[256][MAXB * 3];
#pragma unroll
    for (int s = 0; s < MAXB; s++) {
        sm[threadIdx.x][s * 3 + 0] = acc[s][0];
        sm[threadIdx.x][s * 3 + 1] = acc[s][1];
        sm[threadIdx.x][s * 3 + 2] = acc[s][2];
    }
    __syncthreads();
    if (threadIdx.x < MAXB * 3) {
        float s_ = 0.f;
        for (int t = 0; t < 256; t++) s_ += sm[t][threadIdx.x];
        g_part[blockIdx.x][threadIdx.x] = s_;
    }
}

// ---------------------------------------------------------------------------
// Kernel 2: finalize scene means (1 block, deterministic).
// ---------------------------------------------------------------------------
__global__ void k_final(int b)
{
    int k = threadIdx.x;
    if (k < b * 3) {
        float s_ = 0.f;
        for (int p = 0; p < NPART; p++) s_ += g_part[p][k];
        g_mean[k] = s_ / g_len[k / 3];
    }
}

// ---------------------------------------------------------------------------
// Kernel 3: fused main kernel.
// One warp processes WR contiguous rows; lane owns 8 channels:
//   c = lane*4 + j (j<4),  c = 128 + lane*4 + (j-4) (j>=4)  -> 2x float4 per row.
// Rolling 3-row register window supplies the depthwise conv.
// ---------------------------------------------------------------------------
__global__ __launch_bounds__(256) void k_main(
    const float* __restrict__ feat, const float* __restrict__ coord,
    const float* __restrict__ w_xyz, const float* __restrict__ b_xyz,
    const float* __restrict__ g1, const float* __restrict__ be1,
    const float* __restrict__ w_conv, const float* __restrict__ b_conv,
    const float* __restrict__ g2, const float* __restrict__ be2,
    float* __restrict__ out, int n, int b)
{
    const int lane = threadIdx.x & 31;
    const int gwarp = (blockIdx.x * blockDim.x + threadIdx.x) >> 5;
    const long start = (long)gwarp * WR;
    if (start >= n) return;
    const int end = (int)min((long)(start + WR), (long)n);
    const int cbase = lane * 4;

    // Per-thread channel parameters in registers.
    float wx0[8], wx1[8], wx2[8], bx[8], pg1[8], pb1[8];
    float wc0[8], wc1[8], wc2[8], bc[8], pg2[8], pb2[8];
#pragma unroll
    for (int j = 0; j < 8; j++) {
        int c = (j < 4) ? (cbase + j) : (128 + cbase + (j - 4));
        wx0[j] = w_xyz[c];
        wx1[j] = w_xyz[CCH + c];
        wx2[j] = w_xyz[2 * CCH + c];
        bx[j]  = b_xyz[c];
        pg1[j] = g1[c];  pb1[j] = be1[c];
        wc0[j] = w_conv[3 * c + 0];
        wc1[j] = w_conv[3 * c + 1];
        wc2[j] = w_conv[3 * c + 2];
        bc[j]  = b_conv[c];
        pg2[j] = g2[c];  pb2[j] = be2[c];
    }

    // Compute f = feat + gelu(LN(xyz_c @ W)) for a row; also return raw feat.
    auto compute_f = [&](int r, float* f, float* ft, int& seg) {
        seg = 0;
#pragma unroll
        for (int s = 1; s < MAXB; s++) if (s < b && r >= g_offs[s]) seg = s;
        float mx = g_mean[seg * 3 + 0];
        float my = g_mean[seg * 3 + 1];
        float mz = g_mean[seg * 3 + 2];
        float cx = coord[3 * r + 0] - mx;
        float cy = coord[3 * r + 1] - my;
        float cz = coord[3 * r + 2] - mz;

        float x[8];
        float s1 = 0.f, s2 = 0.f;
#pragma unroll
        for (int j = 0; j < 8; j++) {
            float v = fmaf(cx, wx0[j], fmaf(cy, wx1[j], fmaf(cz, wx2[j], bx[j])));
            x[j] = v;
            s1 += v;
            s2 = fmaf(v, v, s2);
        }
#pragma unroll
        for (int o = 16; o > 0; o >>= 1) {
            s1 += __shfl_xor_sync(0xffffffffu, s1, o);
            s2 += __shfl_xor_sync(0xffffffffu, s2, o);
        }
        const float inv = 1.0f / (float)CCH;
        float mu   = s1 * inv;
        float var  = fmaf(-mu, mu, s2 * inv);
        float rstd = rsqrtf(var + 1e-5f);

        const float4* fp4 = (const float4*)(feat + (long)r * CCH);
        float4 a = fp4[lane];
        float4 q = fp4[32 + lane];
        ft[0] = a.x; ft[1] = a.y; ft[2] = a.z; ft[3] = a.w;
        ft[4] = q.x; ft[5] = q.y; ft[6] = q.z; ft[7] = q.w;

#pragma unroll
        for (int j = 0; j < 8; j++) {
            float t  = (x[j] - mu) * rstd;
            float ln = fmaf(t, pg1[j], pb1[j]);
            float ge = 0.5f * ln * (1.0f + erff(ln * 0.70710678118654752f));
            f[j] = ft[j] + ge;
        }
    };

    float fprev[8], fcur[8], fnext[8], ftc[8], ftn[8];
    int segp, segc, segn;
    float dummy[8];

    if (start > 0) {
        compute_f((int)start - 1, fprev, dummy, segp);
    } else {
#pragma unroll
        for (int j = 0; j < 8; j++) fprev[j] = 0.f;
        segp = -1;
    }
    compute_f((int)start, fcur, ftc, segc);

    for (int r = (int)start; r < end; r++) {
        if (r + 1 < n) {
            compute_f(r + 1, fnext, ftn, segn);
        } else {
#pragma unroll
            for (int j = 0; j < 8; j++) { fnext[j] = 0.f; ftn[j] = 0.f; }
            segn = -2;
        }

        float mp = (segp == segc) ? 1.f : 0.f;
        float mn = (segn == segc) ? 1.f : 0.f;

        float y[8];
        float s1 = 0.f, s2 = 0.f;
#pragma unroll
        for (int j = 0; j < 8; j++) {
            float cv = fmaf(fprev[j] * mp, wc0[j],
                       fmaf(fcur[j], wc1[j],
                       fmaf(fnext[j] * mn, wc2[j], bc[j])));
            float v = ftc[j] + cv;
            y[j] = v;
            s1 += v;
            s2 = fmaf(v, v, s2);
        }
#pragma unroll
        for (int o = 16; o > 0; o >>= 1) {
            s1 += __shfl_xor_sync(0xffffffffu, s1, o);
            s2 += __shfl_xor_sync(0xffffffffu, s2, o);
        }
        const float inv = 1.0f / (float)CCH;
        float mu   = s1 * inv;
        float var  = fmaf(-mu, mu, s2 * inv);
        float rstd = rsqrtf(var + 1e-5f);

        float4 o1, o2;
        {
            float t;
            t = (y[0] - mu) * rstd; o1.x = fmaf(t, pg2[0], pb2[0]);
            t = (y[1] - mu) * rstd; o1.y = fmaf(t, pg2[1], pb2[1]);
            t = (y[2] - mu) * rstd; o1.z = fmaf(t, pg2[2], pb2[2]);
            t = (y[3] - mu) * rstd; o1.w = fmaf(t, pg2[3], pb2[3]);
            t = (y[4] - mu) * rstd; o2.x = fmaf(t, pg2[4], pb2[4]);
            t = (y[5] - mu) * rstd; o2.y = fmaf(t, pg2[5], pb2[5]);
            t = (y[6] - mu) * rstd; o2.z = fmaf(t, pg2[6], pb2[6]);
            t = (y[7] - mu) * rstd; o2.w = fmaf(t, pg2[7], pb2[7]);
        }
        float4* op4 = (float4*)(out + (long)r * CCH);
        op4[lane]      = o1;
        op4[32 + lane] = o2;

        // rotate window
        segp = segc; segc = segn;
#pragma unroll
        for (int j = 0; j < 8; j++) {
            fprev[j] = fcur[j];
            fcur[j]  = fnext[j];
            ftc[j]   = ftn[j];
        }
    }
}

// ---------------------------------------------------------------------------
extern "C" void kernel_launch(void* const* d_in, const int* in_sizes, int n_in,
                              void* d_out, int out_size)
{
    const float* feat    = (const float*)d_in[0];
    const float* coord   = (const float*)d_in[1];
    const void*  lengths = (const void*)d_in[2];
    const float* w_xyz   = (const float*)d_in[3];
    const float* b_xyz   = (const float*)d_in[4];
    const float* g1      = (const float*)d_in[5];
    const float* be1     = (const float*)d_in[6];
    const float* w_conv  = (const float*)d_in[7];
    const float* b_conv  = (const float*)d_in[8];
    const float* g2      = (const float*)d_in[9];
    const float* be2     = (const float*)d_in[10];
    float*       out     = (float*)d_out;

    int n = in_sizes[0] / CCH;
    int b = in_sizes[2];
    if (b > MAXB) b = MAXB;

    k_offs<<<1, 1>>>(lengths, n, b);
    k_partial<<<NPART, 256>>>(coord, n, b);
    k_final<<<1, 32>>>(b);

    int warps  = (n + WR - 1) / WR;
    int blocks = (warps + 7) / 8;
    k_main<<<blocks, 256>>>(feat, coord, w_xyz, b_xyz, g1, be1,
                            w_conv, b_conv, g2, be2, out, n, b);
}

// round 10
// speedup vs baseline: 1.3464x; 1.3464x over previous
#include <cuda_runtime.h>
#include <math.h>

// Problem constants (fixed by the dataset): C=256 channels.
#define CCH   256
#define WR    64      // rows per warp
#define MAXB  8       // scenes
#define NPART 256     // partial-sum blocks for scene means

__device__ float g_part[NPART][MAXB * 3];
__device__ float g_mean[MAXB * 3];
__device__ int   g_offs[MAXB + 1];

// Resolve lengths dtype (int32 vs int64) and build prefix offsets, per-thread.
__device__ __forceinline__ void resolve_offs(const void* __restrict__ lraw,
                                             int n, int b, int* offs, float* len)
{
    const long long* l64 = (const long long*)lraw;
    const int*       l32 = (const int*)lraw;
    long long s64 = 0;
    for (int i = 0; i < b; i++) s64 += l64[i];
    bool is64 = (s64 == (long long)n);
    int o = 0;
    offs[0] = 0;
    for (int i = 0; i < MAXB; i++) {
        long long L = (i < b) ? (is64 ? l64[i] : (long long)l32[i]) : 0;
        o += (int)L;
        offs[i + 1] = (i < b) ? o : n;
        if (len) len[i] = (float)((L < 1) ? 1 : L);
    }
}

// ---------------------------------------------------------------------------
// Kernel 1: deterministic per-block partial sums of coords per scene.
// ---------------------------------------------------------------------------
__global__ __launch_bounds__(256) void k_partial(
    const float* __restrict__ coord, const void* __restrict__ lraw, int n, int b)
{
    int offs[MAXB + 1];
    resolve_offs(lraw, n, b, offs, nullptr);

    float acc[MAXB][3];
#pragma unroll
    for (int s = 0; s < MAXB; s++) { acc[s][0] = 0.f; acc[s][1] = 0.f; acc[s][2] = 0.f; }

    int rows_per_block = (n + gridDim.x - 1) / gridDim.x;
    int r0 = blockIdx.x * rows_per_block;
    int r1 = min(r0 + rows_per_block, n);

    for (int r = r0 + (int)threadIdx.x; r < r1; r += blockDim.x) {
        float x = coord[3 * r + 0];
        float y = coord[3 * r + 1];
        float z = coord[3 * r + 2];
        int seg = 0;
#pragma unroll
        for (int s = 1; s < MAXB; s++) if (s < b && r >= offs[s]) seg = s;
        acc[seg][0] += x; acc[seg][1] += y; acc[seg][2] += z;
    }

    __shared__ float sm[256][MAXB * 3];
#pragma unroll
    for (int s = 0; s < MAXB; s++) {
        sm[threadIdx.x][s * 3 + 0] = acc[s][0];
        sm[threadIdx.x][s * 3 + 1] = acc[s][1];
        sm[threadIdx.x][s * 3 + 2] = acc[s][2];
    }
    __syncthreads();
    if (threadIdx.x < MAXB * 3) {
        float s_ = 0.f;
        for (int t = 0; t < 256; t++) s_ += sm[t][threadIdx.x];
        g_part[blockIdx.x][threadIdx.x] = s_;
    }
}

// ---------------------------------------------------------------------------
// Kernel 2: finalize scene means + publish offsets (1 block, deterministic).
// ---------------------------------------------------------------------------
__global__ void k_final(const void* __restrict__ lraw, int n, int b)
{
    __shared__ int   offs[MAXB + 1];
    __shared__ float len[MAXB];
    if (threadIdx.x == 0) {
        int o_[MAXB + 1]; float l_[MAXB];
        resolve_offs(lraw, n, b, o_, l_);
        for (int i = 0; i <= MAXB; i++) offs[i] = o_[i];
        for (int i = 0; i < MAXB; i++)  len[i]  = l_[i];
    }
    __syncthreads();
    int k = threadIdx.x;
    if (k < b * 3) {
        float s_ = 0.f;
        for (int p = 0; p < NPART; p++) s_ += g_part[p][k];
        g_mean[k] = s_ / len[k / 3];
    }
    if (k <= MAXB) g_offs[k] = offs[k];
}

// ---------------------------------------------------------------------------
// Kernel 3: fused main kernel.
// 128-thread blocks (4 warps). One warp processes WR=64 contiguous rows; lane
// owns 8 channels: c = lane*4 + j (j<4), c = 128 + lane*4 + (j-4) (j>=4).
// All per-channel params live in shared memory (block-shared, conflict-free
// float4 reads) to keep registers low and occupancy high. Segment id tracked
// incrementally (no per-row global scans). Rolling 3-row register window
// supplies the depthwise conv.
// ---------------------------------------------------------------------------
#define LD8(dst, p) { float4 _u = s_par[p][lane]; float4 _v = s_par[p][32 + lane]; \
    dst[0]=_u.x; dst[1]=_u.y; dst[2]=_u.z; dst[3]=_u.w; \
    dst[4]=_v.x; dst[5]=_v.y; dst[6]=_v.z; dst[7]=_v.w; }

__global__ __launch_bounds__(128, 4) void k_main(
    const float* __restrict__ feat, const float* __restrict__ coord,
    const float* __restrict__ w_xyz, const float* __restrict__ b_xyz,
    const float* __restrict__ g1, const float* __restrict__ be1,
    const float* __restrict__ w_conv, const float* __restrict__ b_conv,
    const float* __restrict__ g2, const float* __restrict__ be2,
    float* __restrict__ out, int n, int b)
{
    __shared__ float4 s_par[12][64];     // 12 param arrays x 256 ch
    __shared__ int    s_offs[MAXB + 1];
    __shared__ float  s_mean[MAXB * 3];

    const int tid = threadIdx.x;
    for (int c = tid; c < CCH; c += 128) {
        ((float*)s_par[0])[c]  = w_xyz[c];
        ((float*)s_par[1])[c]  = w_xyz[CCH + c];
        ((float*)s_par[2])[c]  = w_xyz[2 * CCH + c];
        ((float*)s_par[3])[c]  = b_xyz[c];
        ((float*)s_par[4])[c]  = g1[c];
        ((float*)s_par[5])[c]  = be1[c];
        ((float*)s_par[6])[c]  = w_conv[3 * c + 0];
        ((float*)s_par[7])[c]  = w_conv[3 * c + 1];
        ((float*)s_par[8])[c]  = w_conv[3 * c + 2];
        ((float*)s_par[9])[c]  = b_conv[c];
        ((float*)s_par[10])[c] = g2[c];
        ((float*)s_par[11])[c] = be2[c];
    }
    if (tid <= MAXB)    s_offs[tid] = g_offs[tid];
    if (tid < MAXB * 3) s_mean[tid] = g_mean[tid];
    __syncthreads();

    const int lane  = tid & 31;
    const int gwarp = blockIdx.x * 4 + (tid >> 5);
    const int start = gwarp * WR;
    if (start >= n) return;
    const int end = min(start + WR, n);

    // Incremental segment state (rows visited in increasing order).
    int seg = 0;
    {
        int r0 = (start > 0) ? start - 1 : 0;
        while (seg < b - 1 && r0 >= s_offs[seg + 1]) seg++;
    }
    int bnd = s_offs[seg + 1];
    float mx = s_mean[seg * 3 + 0];
    float my = s_mean[seg * 3 + 1];
    float mz = s_mean[seg * 3 + 2];

    const float inv = 1.0f / (float)CCH;

    // f = feat + gelu(LN1(xyz_c @ W)); also returns raw feat row and seg id.
    auto compute_f = [&](int r, float* f, float* ft) -> int {
        while (r >= bnd) {
            seg++;
            bnd = s_offs[seg + 1];
            mx = s_mean[seg * 3 + 0];
            my = s_mean[seg * 3 + 1];
            mz = s_mean[seg * 3 + 2];
        }
        float cx = coord[3 * r + 0] - mx;
        float cy = coord[3 * r + 1] - my;
        float cz = coord[3 * r + 2] - mz;

        float wa[8], wb[8], wc_[8], wd[8];
        LD8(wa, 0); LD8(wb, 1); LD8(wc_, 2); LD8(wd, 3);

        float x[8];
        float s1 = 0.f, s2 = 0.f;
#pragma unroll
        for (int j = 0; j < 8; j++) {
            float v = fmaf(cx, wa[j], fmaf(cy, wb[j], fmaf(cz, wc_[j], wd[j])));
            x[j] = v;
            s1 += v;
            s2 = fmaf(v, v, s2);
        }
#pragma unroll
        for (int o = 16; o > 0; o >>= 1) {
            s1 += __shfl_xor_sync(0xffffffffu, s1, o);
            s2 += __shfl_xor_sync(0xffffffffu, s2, o);
        }
        float mu   = s1 * inv;
        float var  = fmaf(-mu, mu, s2 * inv);
        float rstd = rsqrtf(var + 1e-5f);

        const float4* fp4 = (const float4*)(feat + (long)r * CCH);
        float4 a = fp4[lane];
        float4 q = fp4[32 + lane];
        ft[0] = a.x; ft[1] = a.y; ft[2] = a.z; ft[3] = a.w;
        ft[4] = q.x; ft[5] = q.y; ft[6] = q.z; ft[7] = q.w;

        LD8(wa, 4); LD8(wb, 5);    // g1, be1
#pragma unroll
        for (int j = 0; j < 8; j++) {
            float t  = (x[j] - mu) * rstd;
            float ln = fmaf(t, wa[j], wb[j]);
            float ge = 0.5f * ln * (1.0f + erff(ln * 0.70710678118654752f));
            f[j] = ft[j] + ge;
        }
        return seg;
    };

    float fprev[8], fcur[8], fnext[8], ftc[8], ftn[8];
    int segp, segc, segn;

    if (start > 0) {
        float dummy[8];
        segp = compute_f(start - 1, fprev, dummy);
    } else {
#pragma unroll
        for (int j = 0; j < 8; j++) fprev[j] = 0.f;
        segp = -1;
    }
    segc = compute_f(start, fcur, ftc);

    for (int r = start; r < end; r++) {
        if (r + 1 < n) {
            segn = compute_f(r + 1, fnext, ftn);
        } else {
#pragma unroll
            for (int j = 0; j < 8; j++) { fnext[j] = 0.f; ftn[j] = 0.f; }
            segn = -2;
        }

        float mp = (segp == segc) ? 1.f : 0.f;
        float mn = (segn == segc) ? 1.f : 0.f;

        float wa[8], wb[8], wc_[8], wd[8];
        LD8(wa, 6); LD8(wb, 7); LD8(wc_, 8); LD8(wd, 9);

        float y[8];
        float s1 = 0.f, s2 = 0.f;
#pragma unroll
        for (int j = 0; j < 8; j++) {
            float cv = fmaf(fprev[j] * mp, wa[j],
                       fmaf(fcur[j], wb[j],
                       fmaf(fnext[j] * mn, wc_[j], wd[j])));
            float v = ftc[j] + cv;
            y[j] = v;
            s1 += v;
            s2 = fmaf(v, v, s2);
        }
#pragma unroll
        for (int o = 16; o > 0; o >>= 1) {
            s1 += __shfl_xor_sync(0xffffffffu, s1, o);
            s2 += __shfl_xor_sync(0xffffffffu, s2, o);
        }
        float mu   = s1 * inv;
        float var  = fmaf(-mu, mu, s2 * inv);
        float rstd = rsqrtf(var + 1e-5f);

        LD8(wa, 10); LD8(wb, 11);  // g2, be2
        float4 o1, o2;
        o1.x = fmaf((y[0] - mu) * rstd, wa[0], wb[0]);
        o1.y = fmaf((y[1] - mu) * rstd, wa[1], wb[1]);
        o1.z = fmaf((y[2] - mu) * rstd, wa[2], wb[2]);
        o1.w = fmaf((y[3] - mu) * rstd, wa[3], wb[3]);
        o2.x = fmaf((y[4] - mu) * rstd, wa[4], wb[4]);
        o2.y = fmaf((y[5] - mu) * rstd, wa[5], wb[5]);
        o2.z = fmaf((y[6] - mu) * rstd, wa[6], wb[6]);
        o2.w = fmaf((y[7] - mu) * rstd, wa[7], wb[7]);

        float4* op4 = (float4*)(out + (long)r * CCH);
        op4[lane]      = o1;
        op4[32 + lane] = o2;

        // rotate window
        segp = segc; segc = segn;
#pragma unroll
        for (int j = 0; j < 8; j++) {
            fprev[j] = fcur[j];
            fcur[j]  = fnext[j];
            ftc[j]   = ftn[j];
        }
    }
}

// ---------------------------------------------------------------------------
extern "C" void kernel_launch(void* const* d_in, const int* in_sizes, int n_in,
                              void* d_out, int out_size)
{
    const float* feat    = (const float*)d_in[0];
    const float* coord   = (const float*)d_in[1];
    const void*  lengths = (const void*)d_in[2];
    const float* w_xyz   = (const float*)d_in[3];
    const float* b_xyz   = (const float*)d_in[4];
    const float* g1      = (const float*)d_in[5];
    const float* be1     = (const float*)d_in[6];
    const float* w_conv  = (const float*)d_in[7];
    const float* b_conv  = (const float*)d_in[8];
    const float* g2      = (const float*)d_in[9];
    const float* be2     = (const float*)d_in[10];
    float*       out     = (float*)d_out;

    int n = in_sizes[0] / CCH;
    int b = in_sizes[2];
    if (b > MAXB) b = MAXB;

    k_partial<<<NPART, 256>>>(coord, lengths, n, b);
    k_final<<<1, 32>>>(lengths, n, b);

    int warps  = (n + WR - 1) / WR;
    int blocks = (warps + 3) / 4;
    k_main<<<blocks, 128>>>(feat, coord, w_xyz, b_xyz, g1, be1,
                            w_conv, b_conv, g2, be2, out, n, b);
}